// round 10
// baseline (speedup 1.0000x reference)
#include <cuda_runtime.h>
#include <cuda_bf16.h>
#include <cstdint>

// MaxUnpooling2DMod: out[b, y(idx), x(idx), c] += in[b,h,w,c]
//   in  [8,128,128,64] -> 2^23 floats, out [8,256,256,64] -> 2^25 floats
// decode: out_off = (b << 22) + (idx & ~63) + (lin & 63)
//
// PDL skip-chain (R8): z0,s0,z1,s1,...  z_b triggers after stores (no wait);
// s_b triggers at entry, loads, waits (-> z_b completion), atomics.
// R10: both kernels sized to EXACTLY one resident wave (148 SM x 8 blocks =
// 1184 blocks, 8 warps/block) -> no wave-2 tail, LSU fed at max occupancy
// for the whole kernel.

static constexpr int BLOCK   = 256;
static constexpr int GRID    = 1184;                     // 148 SMs * 8 blocks
static constexpr int THREADS = GRID * BLOCK;             // 303,104

static constexpr int SLAB_F4   = (1 << 22) / 4;          // 1,048,576 float4/slab
static constexpr int QUADS     = (1 << 20) / 4;          // 262,144 quads/batch

__global__ void __launch_bounds__(BLOCK, 8)
zero_slab_kernel(float* __restrict__ out, int slab)
{
    const int t = blockIdx.x * BLOCK + threadIdx.x;
    float4* o4 = reinterpret_cast<float4*>(out) + (size_t)slab * SLAB_F4;
    const float4 z = make_float4(0.f, 0.f, 0.f, 0.f);
    #pragma unroll
    for (int j = 0; j < 4; j++) {                        // ceil(1048576/303104)=4
        int i = t + j * THREADS;
        if (i < SLAB_F4) o4[i] = z;
    }
    asm volatile("griddepcontrol.launch_dependents;" ::: "memory");
}

__global__ void __launch_bounds__(BLOCK, 8)
scatter_kernel(const float* __restrict__ in,
               const int*   __restrict__ idx,
               float*       __restrict__ out,
               int b)
{
    // Release z_{b+1} (disjoint slab) immediately.
    asm volatile("griddepcontrol.launch_dependents;" ::: "memory");

    const int t      = blockIdx.x * BLOCK + threadIdx.x;
    const bool active = (t < QUADS);

    // Streaming loads in flight before the wait.
    float4 v  = make_float4(0.f, 0.f, 0.f, 0.f);
    int4   id = make_int4(0, 0, 0, 0);
    int    e0 = 0;
    if (active) {
        e0 = (b << 20) + (t << 2);                       // 4 consecutive elems
        v  = __ldcs(reinterpret_cast<const float4*>(in)  + (e0 >> 2));
        id = __ldcs(reinterpret_cast<const int4*>(idx)   + (e0 >> 2));
    }

    // Wait for z_b (immediate predecessor) completion: slab b zeroed+visible.
    asm volatile("griddepcontrol.wait;" ::: "memory");

    if (active) {
        float* o = out + (b << 22);
        const int c0 = e0 & 63;                          // e0 multiple of 4
        atomicAdd(o + (id.x & ~63) + (c0 + 0), v.x);
        atomicAdd(o + (id.y & ~63) + (c0 + 1), v.y);
        atomicAdd(o + (id.z & ~63) + (c0 + 2), v.z);
        atomicAdd(o + (id.w & ~63) + (c0 + 3), v.w);
    }
}

extern "C" void kernel_launch(void* const* d_in, const int* in_sizes, int n_in,
                              void* d_out, int out_size)
{
    const float* in  = (const float*)d_in[0];
    const int*   idx = (const int*)d_in[1];
    float*       out = (float*)d_out;

    cudaLaunchAttribute attrs[1];
    attrs[0].id = cudaLaunchAttributeProgrammaticStreamSerialization;
    attrs[0].val.programmaticStreamSerializationAllowed = 1;

    cudaLaunchConfig_t cfg = {};
    cfg.gridDim  = dim3(GRID, 1, 1);
    cfg.blockDim = dim3(BLOCK, 1, 1);
    cfg.stream   = 0;

    for (int b = 0; b < 8; b++) {
        cfg.attrs    = (b == 0) ? nullptr : attrs;       // z0 has no predecessor
        cfg.numAttrs = (b == 0) ? 0 : 1;
        cudaLaunchKernelEx(&cfg, zero_slab_kernel, out, b);

        cfg.attrs = attrs;  cfg.numAttrs = 1;
        cudaLaunchKernelEx(&cfg, scatter_kernel, in, idx, out, b);
    }
}